// round 7
// baseline (speedup 1.0000x reference)
#include <cuda_runtime.h>

// ISTA deconvolution, fused per-row kernel (round 7).
// R6 tap-parity-split math (verified correct) + execution fixes:
//  - partial unroll 8x8: ring indices stay static ((8mb+i+q)&7 = (i+q)&7),
//    code per conv ~3KB (fits L0 I$) instead of ~25KB fully unrolled.
//  - single prologue barrier: pad zeroing is word-exact and disjoint from
//    staging writes (pairs [0,31) + lo(31) + hi(2079) + [2080,2112)).
//  - y recovered from staged E pairs via LDS.64 (register-half unpacks are
//    free for scalar consumers) instead of a global reload.
// Math: eacc[q] = sum_m h[2m]  *E[8t+q+m] -> (c_e[16t+2q], c_e[16t+2q+1])
//       oa[j]   = sum_m h[2m+1]*E[8t+j+m] -> (c_o[16t+2j-1], c_o[16t+2j])
//       u[2q]   = lo(eacc[q]) + hi(oa[q]);  u[2q+1] = hi(eacc[q]) + lo(oa[q+1])
// Closed-form ISTA epilogue: x_T = T*sign(su)*max(|su|-lambda, 0).

#define BDIM 4096
#define LDIM 4096
#define KW   128
#define NTH  256
#define PPL8 266                 // ull per plane
#define NPAIR_ULL (8 * PPL8)     // 2128
#define LAMBDA 0.1f
#define TITER  5.0f

typedef unsigned long long ull;

__device__ __forceinline__ ull pk2(float lo, float hi) {
    ull r;
    asm("mov.b64 %0, {%1, %2};" : "=l"(r) : "f"(lo), "f"(hi));
    return r;
}
__device__ __forceinline__ void unpk2(ull v, float& lo, float& hi) {
    asm("mov.b64 {%0, %1}, %2;" : "=f"(lo), "=f"(hi) : "l"(v));
}
__device__ __forceinline__ ull fma2(ull a, ull b, ull c) {
    ull d;
    asm("fma.rn.f32x2 %0, %1, %2, %3;" : "=l"(d) : "l"(a), "l"(b), "l"(c));
    return d;
}

// ull index of pair p = 8t + c inside the pair-planar array.
#define PIDX(c, t) ((((c) & 7) * PPL8) + ((c) >> 3) + (t))

// Tap-parity-split convolution, 8x8 partial unroll.
__device__ __forceinline__ void conv_split(const ull* __restrict__ ep,
                                           const ulonglong2* __restrict__ hq,
                                           int t,
                                           ull* __restrict__ eacc,
                                           ull* __restrict__ oa)
{
    ull E[8];
    const ull* b0 = ep + t;
#pragma unroll
    for (int c = 0; c < 8; c++) E[c] = b0[c * PPL8];
#pragma unroll
    for (int q = 0; q < 8; q++) eacc[q] = 0ull;
#pragma unroll
    for (int j = 0; j < 9; j++) oa[j] = 0ull;

    ulonglong2 hh = hq[0];
#pragma unroll 1
    for (int mb = 0; mb < 8; mb++) {
        const ull* br = ep + t + mb + 1;          // refill base: pair 8t+8mb+i+8
        const ulonglong2* hb = hq + 8 * mb;
#pragma unroll
        for (int i = 0; i < 8; i++) {
            ull Enew = br[i * PPL8];
            ulonglong2 hn = hb[i + 1];            // hq[64] is a zero pad
#pragma unroll
            for (int q = 0; q < 8; q++) {
                ull Eq = E[(i + q) & 7];          // static index
                eacc[q] = fma2(Eq, hh.x, eacc[q]);
                oa[q]   = fma2(Eq, hh.y, oa[q]);
            }
            oa[8] = fma2(Enew, hh.y, oa[8]);
            E[i] = Enew;                          // (8mb+i)&7 == i
            hh = hn;
        }
    }
}

__global__ __launch_bounds__(NTH, 3)
void ista_row_kernel(const float* __restrict__ y,
                     const float* __restrict__ h,
                     const float* __restrict__ step,
                     float* __restrict__ out)
{
    __shared__ __align__(16) ull sh_ep[NPAIR_ULL];
    __shared__ __align__(16) ulonglong2 sh_h[KW / 2 + 1];   // dup pairs, fwd (+pad)
    __shared__ __align__(16) ulonglong2 sh_hr[KW / 2 + 1];  // dup pairs, rev (+pad)

    const int t = threadIdx.x;
    const int row = blockIdx.x;
    const float* yr = y + (long long)row * LDIM;
    const float s = __ldg(step);

    // ---- prologue: zero pads + stage h + stage y, ONE barrier ----
    // All writes below are to disjoint 32-bit words, so they may proceed
    // concurrently across warps.
    float* epf = reinterpret_cast<float*>(sh_ep);
    if (t < 31) {                              // pairs [0,31): full zero
        sh_ep[(t & 7) * PPL8 + (t >> 3)] = 0ull;
    } else if (t == 32) {                      // lo half of pair 31 (hi is staged)
        epf[2 * (7 * PPL8 + 3) + 0] = 0.0f;
    } else if (t == 33) {                      // hi half of pair 2079 (lo is staged)
        epf[2 * (7 * PPL8 + 259) + 1] = 0.0f;
    } else if (t >= 64 && t < 96) {            // pairs [2080,2112): full zero
        int j = t - 64;
        sh_ep[(j & 7) * PPL8 + 260 + (j >> 3)] = 0ull;
    } else if (t >= 128 && t < 128 + KW / 2) { // h dup pairs
        int u = t - 128;
        float a0 = h[2 * u], a1 = h[2 * u + 1];
        sh_h[u] = make_ulonglong2(pk2(a0, a0), pk2(a1, a1));
        float b0 = h[KW - 1 - 2 * u], b1 = h[KW - 2 - 2 * u];  // reversed
        sh_hr[u] = make_ulonglong2(pk2(b0, b0), pk2(b1, b1));
    } else if (t == 128 + KW / 2) {            // zero pads for unguarded prefetch
        sh_h[KW / 2]  = make_ulonglong2(0ull, 0ull);
        sh_hr[KW / 2] = make_ulonglong2(0ull, 0ull);
    }

    // Stage y (16 floats/thread) into E pairs: xp[j] = y[j-63];
    // thread t owns y[16t..16t+15] -> xp[16t+63 .. 16t+78].
    {
        float v[16];
        const float4* y4 = reinterpret_cast<const float4*>(yr + 16 * t);
#pragma unroll
        for (int i = 0; i < 4; i++) {
            float4 f = __ldg(y4 + i);
            v[4 * i + 0] = f.x; v[4 * i + 1] = f.y;
            v[4 * i + 2] = f.z; v[4 * i + 3] = f.w;
        }
#pragma unroll
        for (int i = 0; i < 7; i++)   // epairs[8t+32+i] = (v[2i+1], v[2i+2])
            sh_ep[PIDX(32 + i, t)] = pk2(v[2 * i + 1], v[2 * i + 2]);
        epf[2 * PIDX(31, t) + 1] = v[0];    // hi of pair 8t+31
        epf[2 * PIDX(39, t) + 0] = v[15];   // lo of pair 8t+39
    }
    __syncthreads();

    // ---- Stage 1: conv(y, h) ----
    ull eacc[8], oa[9];
    conv_split(sh_ep, sh_h, t, eacc, oa);

    // Recover y scalars from staged pairs (LDS.64; halves unpack free).
    // y[16t+2q] = hi(pair 8t+31+q); y[16t+2q+1] = lo(pair 8t+32+q).
    ull P[9];
#pragma unroll
    for (int q = 0; q < 9; q++) P[q] = sh_ep[PIDX(31 + q, t)];
    __syncthreads();   // all conv1 + P reads done before residual overwrite

    float ro[16];
#pragma unroll
    for (int q = 0; q < 8; q++) {
        float el, eh, ol0, oh0, ol1, oh1, plo, phi, nlo, nhi;
        unpk2(eacc[q], el, eh);
        unpk2(oa[q],     ol0, oh0);   // (c_o[16t+2q-1], c_o[16t+2q])
        unpk2(oa[q + 1], ol1, oh1);   // (c_o[16t+2q+1], c_o[16t+2q+2])
        unpk2(P[q],     plo, phi);    // phi = y[16t+2q]
        unpk2(P[q + 1], nlo, nhi);    // nlo = y[16t+2q+1]
        ro[2 * q + 0] = phi - (el + oh0);
        ro[2 * q + 1] = nlo - (eh + ol1);
    }

    // Write residual into E pairs (identical geometry; pads stay zero).
#pragma unroll
    for (int i = 0; i < 7; i++)
        sh_ep[PIDX(32 + i, t)] = pk2(ro[2 * i + 1], ro[2 * i + 2]);
    epf[2 * PIDX(31, t) + 1] = ro[0];
    epf[2 * PIDX(39, t) + 0] = ro[15];
    __syncthreads();

    // ---- Stage 2: conv(resid, h_rev) + closed-form ISTA epilogue ----
    conv_split(sh_ep, sh_hr, t, eacc, oa);

    float xo[16];
#pragma unroll
    for (int q = 0; q < 8; q++) {
        float el, eh, ol0, oh0, ol1, oh1;
        unpk2(eacc[q], el, eh);
        unpk2(oa[q],     ol0, oh0);
        unpk2(oa[q + 1], ol1, oh1);
        float a0 = s * (el + oh0);
        float a1 = s * (eh + ol1);
        xo[2 * q + 0] = copysignf(TITER * fmaxf(fabsf(a0) - LAMBDA, 0.0f), a0);
        xo[2 * q + 1] = copysignf(TITER * fmaxf(fabsf(a1) - LAMBDA, 0.0f), a1);
    }
    float4* o4 = reinterpret_cast<float4*>(out + (long long)row * LDIM + 16 * t);
#pragma unroll
    for (int i = 0; i < 4; i++)
        o4[i] = make_float4(xo[4 * i], xo[4 * i + 1], xo[4 * i + 2], xo[4 * i + 3]);
}

extern "C" void kernel_launch(void* const* d_in, const int* in_sizes, int n_in,
                              void* d_out, int out_size)
{
    const float* y = nullptr;
    const float* h = nullptr;
    const float* s = nullptr;
    for (int i = 0; i < n_in; i++) {
        if (in_sizes[i] == BDIM * LDIM)      y = (const float*)d_in[i];
        else if (in_sizes[i] == KW)          h = (const float*)d_in[i];
        else if (in_sizes[i] == 1)           s = (const float*)d_in[i];
    }
    ista_row_kernel<<<BDIM, NTH>>>(y, h, s, (float*)d_out);
}

// round 8
// speedup vs baseline: 1.0091x; 1.0091x over previous
#include <cuda_runtime.h>

// ISTA deconvolution (round 8): round-2 kernel (best: 162us) made PERSISTENT.
// - 444 CTAs = 148 SMs x 3 resident CTAs -> exactly one wave, no 23%-full
//   tail wave (was ~8% of runtime at grid=4096).
// - Pad zeroing + h staging once per CTA, amortized over ~9 rows (pads are
//   never dirtied by staging/residual writes, geometry identical every row).
// - Two pair-planar SMEM arrays (E=even-start pairs, O=odd-start pairs); all
//   hot-loop operands are conflict-free LDS.64 straight into f32x2 register
//   pairs. No register lane-crossing (R3 lesson). Full unroll (R7 lesson).
// - h as interleaved dup-pair ulonglong2, one LDS.128 per k-pair, prefetched
//   one iteration ahead (no exposed LDS latency on h).
// - Closed-form ISTA epilogue: x_T = T*sign(su)*max(|su|-lambda, 0).

#define BDIM 4096
#define LDIM 4096
#define KW   128
#define NTH  256
#define NCTA 444                 // 148 SMs * 3 CTAs/SM -> single wave
#define PPL8 266                 // ull per plane
#define NPAIR_ULL (8 * PPL8)     // 2128 ull per pair array
#define LAMBDA 0.1f
#define TITER  5.0f

typedef unsigned long long ull;

__device__ __forceinline__ ull pk2(float lo, float hi) {
    ull r;
    asm("mov.b64 %0, {%1, %2};" : "=l"(r) : "f"(lo), "f"(hi));
    return r;
}
__device__ __forceinline__ void unpk2(ull v, float& lo, float& hi) {
    asm("mov.b64 {%0, %1}, %2;" : "=f"(lo), "=f"(hi) : "l"(v));
}
__device__ __forceinline__ ull fma2(ull a, ull b, ull c) {
    ull d;
    asm("fma.rn.f32x2 %0, %1, %2, %3;" : "=l"(d) : "l"(a), "l"(b), "l"(c));
    return d;
}

// ull index of pair p = 8t + c inside a pair-planar array.
#define PIDX(c, t) ((((c) & 7) * PPL8) + ((c) >> 3) + (t))

// 16 outputs (8 f32x2 accumulators) per thread. E/O rings LDS.64-fed, fully
// unrolled (static ring indices); h dup-pairs prefetched one iteration ahead.
__device__ __forceinline__ void conv16(const ull* __restrict__ ep,
                                       const ull* __restrict__ op,
                                       const ulonglong2* __restrict__ hq,
                                       int t, ull* __restrict__ acc)
{
    ull E[8], O[8];
#pragma unroll
    for (int c = 0; c < 8; c++) {
        E[c] = ep[c * PPL8 + t];
        O[c] = op[c * PPL8 + t];
    }
#pragma unroll
    for (int q = 0; q < 8; q++) acc[q] = 0ull;

    ulonglong2 hh = hq[0];
#pragma unroll
    for (int m = 0; m < KW / 2; m++) {
        // Unguarded reads: pairs up to 8t+71 (max 2111) are zero-padded;
        // hq[64] is a zero pad.
        ull Enew = ep[PIDX(m + 8, t)];
        ull Onew = op[PIDX(m + 8, t)];
        ulonglong2 hn = hq[m + 1];
#pragma unroll
        for (int q = 0; q < 8; q++) {
            acc[q] = fma2(E[(m + q) & 7], hh.x, acc[q]);
            acc[q] = fma2(O[(m + q) & 7], hh.y, acc[q]);
        }
        E[m & 7] = Enew;
        O[m & 7] = Onew;
        hh = hn;
    }
}

__global__ __launch_bounds__(NTH, 3)
void ista_persistent_kernel(const float* __restrict__ y,
                            const float* __restrict__ h,
                            const float* __restrict__ step,
                            float* __restrict__ out)
{
    __shared__ __align__(16) ull sh_ep[NPAIR_ULL];
    __shared__ __align__(16) ull sh_op[NPAIR_ULL];
    __shared__ __align__(16) ulonglong2 sh_h[KW / 2 + 1];   // dup pairs fwd (+pad)
    __shared__ __align__(16) ulonglong2 sh_hr[KW / 2 + 1];  // dup pairs rev (+pad)

    const int t = threadIdx.x;
    const float s = __ldg(step);
    float* epf = reinterpret_cast<float*>(sh_ep);

    // ---- once per CTA: zero everything, stage h (amortized over ~9 rows) ----
    for (int i = t; i < NPAIR_ULL; i += NTH) { sh_ep[i] = 0ull; sh_op[i] = 0ull; }
    if (t < KW / 2) {
        float a0 = h[2 * t], a1 = h[2 * t + 1];
        sh_h[t] = make_ulonglong2(pk2(a0, a0), pk2(a1, a1));
        float b0 = h[KW - 1 - 2 * t], b1 = h[KW - 2 - 2 * t];   // reversed kernel
        sh_hr[t] = make_ulonglong2(pk2(b0, b0), pk2(b1, b1));
    }
    if (t == KW / 2) {   // zero pads for the unguarded h prefetch
        sh_h[KW / 2]  = make_ulonglong2(0ull, 0ull);
        sh_hr[KW / 2] = make_ulonglong2(0ull, 0ull);
    }

    for (int row = blockIdx.x; row < BDIM; row += NCTA) {
        const float* yr = y + (long long)row * LDIM;

        // Barrier: (first iter) init complete; (later iters) previous row's
        // conv2 reads complete before restaging.
        __syncthreads();

        // Stage y (16 floats/thread): xp[j] = y[j-63];
        // thread t owns y[16t..16t+15] -> xp[16t+63 .. 16t+78].
        {
            float v[16];
            const float4* y4 = reinterpret_cast<const float4*>(yr + 16 * t);
#pragma unroll
            for (int i = 0; i < 4; i++) {
                float4 f = __ldg(y4 + i);
                v[4 * i + 0] = f.x; v[4 * i + 1] = f.y;
                v[4 * i + 2] = f.z; v[4 * i + 3] = f.w;
            }
#pragma unroll
            for (int i = 0; i < 8; i++)   // opairs[8t+31+i] = (v[2i], v[2i+1])
                sh_op[PIDX(31 + i, t)] = pk2(v[2 * i], v[2 * i + 1]);
#pragma unroll
            for (int i = 0; i < 7; i++)   // epairs[8t+32+i] = (v[2i+1], v[2i+2])
                sh_ep[PIDX(32 + i, t)] = pk2(v[2 * i + 1], v[2 * i + 2]);
            epf[2 * PIDX(31, t) + 1] = v[0];    // hi of epair 8t+31
            epf[2 * PIDX(39, t) + 0] = v[15];   // lo of epair 8t+39
        }
        __syncthreads();

        // ---- Stage 1: conv(y, h); residual = y - conv ----
        ull acc[8];
        conv16(sh_ep, sh_op, sh_h, t, acc);

        ull r2[8];
        {
            const ull neg1 = pk2(-1.0f, -1.0f);
#pragma unroll
            for (int q = 0; q < 8; q++) {
                ull yp = sh_op[PIDX(31 + q, t)];   // (y[16t+2q], y[16t+2q+1])
                r2[q] = fma2(acc[q], neg1, yp);    // resid = y - conv
            }
        }
        __syncthreads();   // all conv1 reads done before residual overwrite

        // Overwrite pair arrays with residual (identical geometry; pads
        // remain zero — never touched).
        {
            float lo[8], hi[8];
#pragma unroll
            for (int q = 0; q < 8; q++) unpk2(r2[q], lo[q], hi[q]);
#pragma unroll
            for (int q = 0; q < 8; q++)
                sh_op[PIDX(31 + q, t)] = r2[q];
#pragma unroll
            for (int i = 0; i < 7; i++)
                sh_ep[PIDX(32 + i, t)] = pk2(hi[i], lo[i + 1]);
            epf[2 * PIDX(31, t) + 1] = lo[0];
            epf[2 * PIDX(39, t) + 0] = hi[7];
        }
        __syncthreads();

        // ---- Stage 2: conv(resid, h_rev) + closed-form ISTA epilogue ----
        conv16(sh_ep, sh_op, sh_hr, t, acc);

        float xo[16];
#pragma unroll
        for (int q = 0; q < 8; q++) {
            float u0, u1;
            unpk2(acc[q], u0, u1);
            float a0 = s * u0;
            float a1 = s * u1;
            xo[2 * q + 0] = copysignf(TITER * fmaxf(fabsf(a0) - LAMBDA, 0.0f), a0);
            xo[2 * q + 1] = copysignf(TITER * fmaxf(fabsf(a1) - LAMBDA, 0.0f), a1);
        }
        float4* o4 = reinterpret_cast<float4*>(out + (long long)row * LDIM + 16 * t);
#pragma unroll
        for (int i = 0; i < 4; i++)
            o4[i] = make_float4(xo[4 * i], xo[4 * i + 1], xo[4 * i + 2], xo[4 * i + 3]);
    }
}

extern "C" void kernel_launch(void* const* d_in, const int* in_sizes, int n_in,
                              void* d_out, int out_size)
{
    const float* y = nullptr;
    const float* h = nullptr;
    const float* s = nullptr;
    for (int i = 0; i < n_in; i++) {
        if (in_sizes[i] == BDIM * LDIM)      y = (const float*)d_in[i];
        else if (in_sizes[i] == KW)          h = (const float*)d_in[i];
        else if (in_sizes[i] == 1)           s = (const float*)d_in[i];
    }
    ista_persistent_kernel<<<NCTA, NTH>>>(y, h, s, (float*)d_out);
}